// round 12
// baseline (speedup 1.0000x reference)
#include <cuda_runtime.h>
#include <cuda_bf16.h>
#include <math.h>
#include <cstdint>
#include <stdint.h>

#define BSZ 16384
#define HD 512
#define NL 3
#define HD4 2048
#define SEG BSZ

// bf16 GEMM tiles
#define BN 128
#define BK 64                         // elements
#define PADE 72                       // smem row stride in bf16 elements (144B)
#define SMEM_B128 (3*(128+BN)*PADE*2) // 3-stage, BM=128

// fused GEMM+LN tile: 64 x 512, 2-stage
#define BMF 64
#define STF_EL ((BMF+HD)*PADE)
#define SMEM_LN_BYTES (2*STF_EL*2)

// ---------------- scratch ----------------
__device__ float d_bc[6*HD];
__device__ int   d_cnt[2];
__device__ int   d_idx[2][BSZ];
__device__ int   d_pos[2][BSZ];
__device__ float d_xbuf[(size_t)2*SEG*HD];
__device__ float d_genb[(size_t)2*SEG*HD];
__device__ float d_prior_h[2*HD];
__device__ float d_prior  [2*HD];

__device__ __align__(16) __nv_bfloat16 d_srcC16[(size_t)2*SEG*HD];
__device__ __align__(16) __nv_bfloat16 d_tgtC16[(size_t)2*SEG*HD];
__device__ __align__(16) __nv_bfloat16 d_x16  [(size_t)2*SEG*HD];
__device__ __align__(16) __nv_bfloat16 d_hb16 [(size_t)2*SEG*HD4];
__device__ __align__(16) __nv_bfloat16 d_aow16[(size_t)6*HD*HD];
__device__ __align__(16) __nv_bfloat16 d_wvT16[(size_t)6*HD*HD];
__device__ __align__(16) __nv_bfloat16 d_Wc16 [(size_t)6*HD*HD];
__device__ __align__(16) __nv_bfloat16 d_ipw16[(size_t)2*HD*HD];
__device__ __align__(16) __nv_bfloat16 d_opw16[(size_t)2*HD*HD];
__device__ __align__(16) __nv_bfloat16 d_f1w16[(size_t)6*HD4*HD];
__device__ __align__(16) __nv_bfloat16 d_f2w16[(size_t)6*HD*HD4];

// ---------------- helpers ----------------
__device__ __forceinline__ float gelu_exact(float x){
    return 0.5f*x*(1.0f+erff(x*0.70710678118654752440f));
}
__device__ __forceinline__ unsigned int packbf(float a, float b){
    __nv_bfloat162 p; p.x = __float2bfloat16_rn(a); p.y = __float2bfloat16_rn(b);
    return *reinterpret_cast<unsigned int*>(&p);
}
__device__ __forceinline__ void cpasync16(unsigned int s, const void* g){
    asm volatile("cp.async.cg.shared.global [%0], [%1], 16;\n" :: "r"(s), "l"(g));
}
__device__ __forceinline__ void cpasync_commit(){
    asm volatile("cp.async.commit_group;\n");
}
__device__ __forceinline__ void cpasync_wait1(){
    asm volatile("cp.async.wait_group 1;\n" ::: "memory");
}
__device__ __forceinline__ void cpasync_wait0(){
    asm volatile("cp.async.wait_group 0;\n" ::: "memory");
}
__device__ __forceinline__ void ldsm_x4(unsigned int a, unsigned int &r0, unsigned int &r1,
                                        unsigned int &r2, unsigned int &r3){
    asm volatile("ldmatrix.sync.aligned.m8n8.x4.shared.b16 {%0,%1,%2,%3}, [%4];"
                 : "=r"(r0),"=r"(r1),"=r"(r2),"=r"(r3) : "r"(a));
}
__device__ __forceinline__ void mma_bf16(float* d, const unsigned int* a, const unsigned int* b){
    asm volatile(
        "mma.sync.aligned.m16n8k16.row.col.f32.bf16.bf16.f32 "
        "{%0,%1,%2,%3}, {%4,%5,%6,%7}, {%8,%9}, {%0,%1,%2,%3};"
        : "+f"(d[0]),"+f"(d[1]),"+f"(d[2]),"+f"(d[3])
        : "r"(a[0]),"r"(a[1]),"r"(a[2]),"r"(a[3]),"r"(b[0]),"r"(b[1]));
}

// ---------------- bf16 GEMM: C[z][M,N] = A[z]@W[z]^T + bias ----------------
// EPI: 0 none, 1 gelu.  OUTM: 0 fp32 only, 1 fp32+bf16 shadow, 2 bf16 only.
// BM=128 x BN=128, 3-stage cp.async ring, one __syncthreads per K-iteration.
template<int EPI, int OUTM>
__global__ void __launch_bounds__(256, 2) mm16(
    const __nv_bfloat16* __restrict__ A, size_t As_,
    const __nv_bfloat16* __restrict__ W, size_t Ws_,
    const float* __restrict__ bias, size_t bs_,
    float* __restrict__ C, __nv_bfloat16* __restrict__ C16, size_t Cs_,
    int N, int K, int Mstatic, const int* __restrict__ cnt)
{
    constexpr int TBM = 128;
    constexpr int STG = (TBM+BN)*PADE;

    const int z  = blockIdx.z;
    const int Mv = cnt ? cnt[z] : Mstatic;
    const int m0 = blockIdx.y * TBM;
    if (m0 >= Mv) return;
    const int n0 = blockIdx.x * BN;
    A += (size_t)z * As_;
    W += (size_t)z * Ws_;
    if (OUTM != 2) C   += (size_t)z * Cs_;
    if (OUTM != 0) C16 += (size_t)z * Cs_;
    const float* bptr = bias ? (bias + (size_t)z * bs_) : nullptr;

    extern __shared__ __nv_bfloat16 smem16[];
    const unsigned int smem_u32 = (unsigned int)__cvta_generic_to_shared(smem16);

    const int tid  = threadIdx.x;
    const int wid  = tid >> 5;
    const int lane = tid & 31;
    const int wm   = wid & 1;
    const int wn   = wid >> 1;

    const int arow = (lane & 7) + ((lane >> 3) & 1) * 8;
    const int acol = ((lane >> 4) & 1) * 8;
    const int brow = (lane & 7) + ((lane >> 4) & 1) * 8;
    const int bcol = ((lane >> 3) & 1) * 8;

    unsigned int a_off[4], b_off[2];
    #pragma unroll
    for (int i=0;i<4;i++) a_off[i] = (unsigned int)(((wm*64 + i*16 + arow)*PADE + acol)*2);
    #pragma unroll
    for (int p=0;p<2;p++) b_off[p] = (unsigned int)((TBM*PADE + (wn*32 + p*16 + brow)*PADE + bcol)*2);

    float acc[4][4][4];
    #pragma unroll
    for (int i=0;i<4;i++)
        #pragma unroll
        for (int j=0;j<4;j++)
            #pragma unroll
            for (int r=0;r<4;r++) acc[i][j][r]=0.f;

    auto load_stage = [&](int s, int k0){
        const unsigned int base = smem_u32 + (unsigned int)(s*STG*2);
        #pragma unroll
        for (int it=0; it<4; it++){
            int c  = tid + it*256;          // 0..1023
            int r  = c >> 3;                // 0..127
            int kq = (c & 7) * 8;
            unsigned int off = (unsigned int)((r*PADE + kq)*2);
            cpasync16(base + off,                                  &A[(size_t)(m0+r)*K + k0 + kq]);
            cpasync16(base + (unsigned int)(TBM*PADE*2) + off,     &W[(size_t)(n0+r)*K + k0 + kq]);
        }
        cpasync_commit();
    };

    const int NIT = K / BK;
    load_stage(0, 0);
    load_stage(1, BK);

    for (int i=0; i<NIT; i++){
        if (i < NIT-1) cpasync_wait1(); else cpasync_wait0();
        __syncthreads();
        if (i + 2 < NIT) load_stage((i+2)%3, (i+2)*BK);

        const unsigned int sb = smem_u32 + (unsigned int)((i%3)*STG*2);
        #pragma unroll
        for (int kk=0; kk<BK; kk+=16){
            unsigned int a[4][4], b[4][2];
            #pragma unroll
            for (int ii=0;ii<4;ii++)
                ldsm_x4(sb + a_off[ii] + (unsigned int)(kk*2), a[ii][0],a[ii][1],a[ii][2],a[ii][3]);
            #pragma unroll
            for (int p=0;p<2;p++)
                ldsm_x4(sb + b_off[p] + (unsigned int)(kk*2),
                        b[2*p][0], b[2*p][1], b[2*p+1][0], b[2*p+1][1]);
            #pragma unroll
            for (int ii=0;ii<4;ii++)
                #pragma unroll
                for (int j=0;j<4;j++)
                    mma_bf16(acc[ii][j], a[ii], b[j]);
        }
    }

    const int g   = lane >> 2;
    const int tig = lane & 3;
    #pragma unroll
    for (int i=0;i<4;i++){
        int row0 = m0 + wm*64 + i*16 + g;
        int row1 = row0 + 8;
        #pragma unroll
        for (int j=0;j<4;j++){
            int col = n0 + wn*32 + j*8 + 2*tig;
            float b0 = bptr ? bptr[col]   : 0.f;
            float b1 = bptr ? bptr[col+1] : 0.f;
            float v0 = acc[i][j][0] + b0, v1 = acc[i][j][1] + b1;
            float v2 = acc[i][j][2] + b0, v3 = acc[i][j][3] + b1;
            if (EPI==1){ v0=gelu_exact(v0); v1=gelu_exact(v1); v2=gelu_exact(v2); v3=gelu_exact(v3); }
            if (row0 < Mv){
                if (OUTM != 2) *(float2*)&C[(size_t)row0*N + col] = make_float2(v0,v1);
                if (OUTM != 0) *(unsigned int*)&C16[(size_t)row0*N + col] = packbf(v0,v1);
            }
            if (row1 < Mv){
                if (OUTM != 2) *(float2*)&C[(size_t)row1*N + col] = make_float2(v2,v3);
                if (OUTM != 0) *(unsigned int*)&C16[(size_t)row1*N + col] = packbf(v2,v3);
            }
        }
    }
}

// ---------------- fused bf16 GEMM + residual + LayerNorm (N = 512) ----------------
__global__ void __launch_bounds__(256, 1) mm16_ln(
    const __nv_bfloat16* __restrict__ A, size_t As_,
    const __nv_bfloat16* __restrict__ W, size_t Ws_,
    const float* __restrict__ bias, size_t bs_,
    const float* __restrict__ Xres, size_t Xs_,
    const float* __restrict__ lng, const float* __restrict__ lnb, size_t lns_,
    float* __restrict__ Out, __nv_bfloat16* __restrict__ Out16, size_t Os_,
    int K, const int* __restrict__ cnt)
{
    const int z  = blockIdx.z;
    const int Mv = cnt[z];
    const int m0 = blockIdx.y * BMF;
    if (m0 >= Mv) return;
    A     += (size_t)z * As_;
    W     += (size_t)z * Ws_;
    Xres  += (size_t)z * Xs_;
    Out   += (size_t)z * Os_;
    Out16 += (size_t)z * Os_;
    const float* bptr = bias + (size_t)z * bs_;
    const float* gptr = lng  + (size_t)z * lns_;
    const float* hptr = lnb  + (size_t)z * lns_;

    extern __shared__ __nv_bfloat16 smem16[];
    const unsigned int smem_u32 = (unsigned int)__cvta_generic_to_shared(smem16);
    float* smf = reinterpret_cast<float*>(smem16);

    const int tid  = threadIdx.x;
    const int wid  = tid >> 5;
    const int lane = tid & 31;
    const int wm   = wid & 1;     // 2 m-halves of 32
    const int wn   = wid >> 1;    // 4 n-quarters of 128

    const int arow = (lane & 7) + ((lane >> 3) & 1) * 8;
    const int acol = ((lane >> 4) & 1) * 8;
    const int brow = (lane & 7) + ((lane >> 4) & 1) * 8;
    const int bcol = ((lane >> 3) & 1) * 8;

    unsigned int a_off[2], b_off[8];
    #pragma unroll
    for (int i=0;i<2;i++) a_off[i] = (unsigned int)(((wm*32 + i*16 + arow)*PADE + acol)*2);
    #pragma unroll
    for (int p=0;p<8;p++) b_off[p] = (unsigned int)((BMF*PADE + (wn*128 + p*16 + brow)*PADE + bcol)*2);

    float acc[2][16][4];
    #pragma unroll
    for (int i=0;i<2;i++)
        #pragma unroll
        for (int j=0;j<16;j++)
            #pragma unroll
            for (int r=0;r<4;r++) acc[i][j][r]=0.f;

    auto load_stage = [&](int s, int k0){
        const unsigned int base = smem_u32 + (unsigned int)(s*STF_EL*2);
        #pragma unroll
        for (int it=0; it<2; it++){
            int c  = tid + it*256;
            int r  = c >> 3;
            int kq = (c & 7) * 8;
            cpasync16(base + (unsigned int)((r*PADE + kq)*2), &A[(size_t)(m0+r)*K + k0 + kq]);
        }
        #pragma unroll
        for (int it=0; it<16; it++){
            int c  = tid + it*256;
            int r  = c >> 3;
            int kq = (c & 7) * 8;
            cpasync16(base + (unsigned int)((BMF*PADE + r*PADE + kq)*2), &W[(size_t)r*K + k0 + kq]);
        }
        cpasync_commit();
    };

    const int NIT = K / BK;
    load_stage(0, 0);

    for (int i=0; i<NIT; i++){
        cpasync_wait0();
        __syncthreads();
        if (i + 1 < NIT) load_stage((i+1)&1, (i+1)*BK);

        const unsigned int sb = smem_u32 + (unsigned int)((i&1)*STF_EL*2);
        #pragma unroll
        for (int kk=0; kk<BK; kk+=16){
            unsigned int a[2][4], b[16][2];
            #pragma unroll
            for (int ii=0;ii<2;ii++)
                ldsm_x4(sb + a_off[ii] + (unsigned int)(kk*2), a[ii][0],a[ii][1],a[ii][2],a[ii][3]);
            #pragma unroll
            for (int p=0;p<8;p++)
                ldsm_x4(sb + b_off[p] + (unsigned int)(kk*2),
                        b[2*p][0], b[2*p][1], b[2*p+1][0], b[2*p+1][1]);
            #pragma unroll
            for (int ii=0;ii<2;ii++)
                #pragma unroll
                for (int j=0;j<16;j++)
                    mma_bf16(acc[ii][j], a[ii], b[j]);
        }
    }
    __syncthreads();

    const int g   = lane >> 2;
    const int tig = lane & 3;
    #pragma unroll
    for (int i=0;i<2;i++){
        int row0 = m0 + wm*32 + i*16 + g;
        int row1 = row0 + 8;
        #pragma unroll
        for (int j=0;j<16;j++){
            int col = wn*128 + j*8 + 2*tig;
            float b0 = bptr[col], b1 = bptr[col+1];
            if (row0 < Mv){
                float2 x = *(const float2*)&Xres[(size_t)row0*HD + col];
                acc[i][j][0] += b0 + x.x;
                acc[i][j][1] += b1 + x.y;
            }
            if (row1 < Mv){
                float2 x = *(const float2*)&Xres[(size_t)row1*HD + col];
                acc[i][j][2] += b0 + x.x;
                acc[i][j][3] += b1 + x.y;
            }
        }
    }

    float S[2][2], Q[2][2];
    #pragma unroll
    for (int i=0;i<2;i++)
        #pragma unroll
        for (int h=0;h<2;h++){
            float s=0.f, q=0.f;
            #pragma unroll
            for (int j=0;j<16;j++){
                float v0=acc[i][j][2*h], v1=acc[i][j][2*h+1];
                s += v0+v1; q += v0*v0+v1*v1;
            }
            s += __shfl_xor_sync(0xffffffffu, s, 1);
            s += __shfl_xor_sync(0xffffffffu, s, 2);
            q += __shfl_xor_sync(0xffffffffu, q, 1);
            q += __shfl_xor_sync(0xffffffffu, q, 2);
            S[i][h]=s; Q[i][h]=q;
        }
    float* redS = smf;
    float* redQ = smf + 256;
    if (tig==0){
        #pragma unroll
        for (int i=0;i<2;i++)
            #pragma unroll
            for (int h=0;h<2;h++){
                int lr = wm*32 + i*16 + g + h*8;
                redS[lr*4+wn] = S[i][h];
                redQ[lr*4+wn] = Q[i][h];
            }
    }
    __syncthreads();

    #pragma unroll
    for (int i=0;i<2;i++){
        #pragma unroll
        for (int h=0;h<2;h++){
            int lr  = wm*32 + i*16 + g + h*8;
            int row = m0 + lr;
            if (row >= Mv) continue;
            float s = redS[lr*4+0]+redS[lr*4+1]+redS[lr*4+2]+redS[lr*4+3];
            float q = redQ[lr*4+0]+redQ[lr*4+1]+redQ[lr*4+2]+redQ[lr*4+3];
            float mean = s*(1.f/512.f);
            float var  = q*(1.f/512.f) - mean*mean;
            float rs   = rsqrtf(var + 1e-5f);
            #pragma unroll
            for (int j=0;j<16;j++){
                int col = wn*128 + j*8 + 2*tig;
                float g0=gptr[col], g1=gptr[col+1], h0=hptr[col], h1=hptr[col+1];
                float v0=(acc[i][j][2*h  ]-mean)*rs*g0+h0;
                float v1=(acc[i][j][2*h+1]-mean)*rs*g1+h1;
                *(float2*)&Out[(size_t)row*HD + col] = make_float2(v0,v1);
                *(unsigned int*)&Out16[(size_t)row*HD + col] = packbf(v0,v1);
            }
        }
    }
}

// ---------------- merged weight conversion (5 segments in one launch) ----------------
__global__ void cvt_all_kernel(
    const float* s0, __nv_bfloat16* d0, int n0,
    const float* s1, __nv_bfloat16* d1, int n1,
    const float* s2, __nv_bfloat16* d2, int n2,
    const float* s3, __nv_bfloat16* d3, int n3,
    const float* s4, __nv_bfloat16* d4, int n4)
{
    const float* s; __nv_bfloat16* d; int n;
    switch (blockIdx.y){
        case 0: s=s0; d=d0; n=n0; break;
        case 1: s=s1; d=d1; n=n1; break;
        case 2: s=s2; d=d2; n=n2; break;
        case 3: s=s3; d=d3; n=n3; break;
        default: s=s4; d=d4; n=n4; break;
    }
    int i = (blockIdx.x*blockDim.x + threadIdx.x)*4;
    if (i >= n) return;
    float4 v = *(const float4*)&s[i];
    *(uint2*)&d[i] = make_uint2(packbf(v.x,v.y), packbf(v.z,v.w));
}

// ---------------- misc kernels ----------------
__global__ void build_index_kernel(const int* __restrict__ mt)
{
    if (threadIdx.x==0){ d_cnt[0]=0; d_cnt[1]=0; }
    __syncthreads();
    for (int b=threadIdx.x; b<BSZ; b+=blockDim.x){
        int m = mt[b];
        if (m==1){ int p=atomicAdd(&d_cnt[0],1); d_idx[0][p]=b; d_pos[0][b]=p; }
        else if (m==2){ int p=atomicAdd(&d_cnt[1],1); d_idx[1][p]=b; d_pos[1][b]=p; }
    }
}

__global__ void __launch_bounds__(128) gather_kernel(
    const float* __restrict__ img, const float* __restrict__ text)
{
    int gi = blockIdx.y;
    int c  = blockIdx.x;
    if (c >= d_cnt[gi]) return;
    int r = d_idx[gi][c];
    const float* src = gi ? text : img;
    const float* tgt = gi ? img  : text;
    int t = threadIdx.x;
    size_t drow = (size_t)gi*SEG + c;
    float4 sv = ((const float4*)src)[(size_t)r*128+t];
    float4 tv = ((const float4*)tgt)[(size_t)r*128+t];
    *(uint2*)&d_srcC16[drow*HD + t*4] = make_uint2(packbf(sv.x,sv.y), packbf(sv.z,sv.w));
    *(uint2*)&d_tgtC16[drow*HD + t*4] = make_uint2(packbf(tv.x,tv.y), packbf(tv.z,tv.w));
}

__global__ void transpose_wv_kernel(const float* __restrict__ qkv_w)
{
    __shared__ float tile[32][33];
    int bz = blockIdx.z;
    const float* src = qkv_w + (size_t)bz*3*HD*HD + (size_t)2*HD*HD;
    int j0 = blockIdx.y*32, k0 = blockIdx.x*32;
    int tx = threadIdx.x, ty = threadIdx.y;
    #pragma unroll
    for (int r=0;r<32;r+=8)
        tile[ty+r][tx] = src[(size_t)(j0+ty+r)*HD + k0+tx];
    __syncthreads();
    __nv_bfloat16* dst = d_wvT16 + (size_t)bz*HD*HD;
    #pragma unroll
    for (int r=0;r<32;r+=8)
        dst[(size_t)(k0+ty+r)*HD + j0+tx] = __float2bfloat16_rn(tile[tx][ty+r]);
}

__global__ void __launch_bounds__(256) bc_kernel(const float* __restrict__ ao_w,
                          const float* __restrict__ ao_b,
                          const float* __restrict__ qkv_b)
{
    int z = blockIdx.x;
    int n = blockIdx.y*8 + (threadIdx.x>>5);
    int lane = threadIdx.x&31;
    const float* ao = ao_w + (size_t)z*HD*HD + (size_t)n*HD;
    const float* bv = qkv_b + (size_t)z*3*HD + 2*HD;
    float s=0.f;
    #pragma unroll
    for (int j=lane*4;j<HD;j+=128){
        float4 a = *(const float4*)&ao[j];
        float4 b = *(const float4*)&bv[j];
        s += a.x*b.x + a.y*b.y + a.z*b.z + a.w*b.w;
    }
    #pragma unroll
    for (int off=16;off;off>>=1) s += __shfl_down_sync(0xffffffffu,s,off);
    if (lane==0) d_bc[(size_t)z*HD+n] = s + ao_b[(size_t)z*HD+n];
}

__global__ void prior_mm_kernel(const float* __restrict__ x, const float* __restrict__ W,
                                const float* __restrict__ b, float* __restrict__ out,
                                int K, int N, int dogelu)
{
    int gw = (blockIdx.x*blockDim.x + threadIdx.x)>>5;
    int lane = threadIdx.x & 31;
    if (gw >= N) return;
    float s=0.f;
    for (int k=lane;k<K;k+=32) s += x[k]*W[(size_t)gw*K+k];
    #pragma unroll
    for (int off=16;off;off>>=1) s += __shfl_down_sync(0xffffffffu,s,off);
    if (lane==0){ s += b[gw]; out[gw] = dogelu ? gelu_exact(s) : s; }
}

__global__ void __launch_bounds__(128) final_kernel(
    const float* __restrict__ img, const float* __restrict__ text,
    const int* __restrict__ mtA, const float* __restrict__ rw,
    float* __restrict__ out)
{
    int b = blockIdx.x, t = threadIdx.x;
    int mt = mtA[b];
    float4 iv = ((const float4*)img )[(size_t)b*128+t];
    float4 tv = ((const float4*)text)[(size_t)b*128+t];
    float4 oi = iv, ot = tv;
    if (mt==3){
        oi = ((const float4*)d_prior)[t];
        ot = ((const float4*)d_prior)[128+t];
    } else if (mt==2){
        float r = rw[1], q = 1.f - r;
        float4 gv = ((const float4*)d_genb)[((size_t)SEG + d_pos[1][b])*128+t];
        oi.x=r*iv.x+q*gv.x; oi.y=r*iv.y+q*gv.y; oi.z=r*iv.z+q*gv.z; oi.w=r*iv.w+q*gv.w;
    } else if (mt==1){
        float r = rw[0], q = 1.f - r;
        float4 gv = ((const float4*)d_genb)[(size_t)d_pos[0][b]*128+t];
        ot.x=r*tv.x+q*gv.x; ot.y=r*tv.y+q*gv.y; ot.z=r*tv.z+q*gv.z; ot.w=r*tv.w+q*gv.w;
    }
    ((float4*)out)[(size_t)b*128+t] = oi;
    ((float4*)out)[(size_t)BSZ*128 + (size_t)b*128+t] = ot;
}

// ---------------- host orchestration ----------------
extern "C" void kernel_launch(void* const* d_in, const int* in_sizes, int n_in,
                              void* d_out, int out_size)
{
    const float* img  = (const float*)d_in[0];
    const float* text = (const float*)d_in[1];
    const float* ipw  = (const float*)d_in[2];
    const float* ipb  = (const float*)d_in[3];
    const float* qkvw = (const float*)d_in[4];
    const float* qkvb = (const float*)d_in[5];
    const float* aow  = (const float*)d_in[6];
    const float* aob  = (const float*)d_in[7];
    const float* ln1g = (const float*)d_in[8];
    const float* ln1b = (const float*)d_in[9];
    const float* ln2g = (const float*)d_in[10];
    const float* ln2b = (const float*)d_in[11];
    const float* f1w  = (const float*)d_in[12];
    const float* f1b  = (const float*)d_in[13];
    const float* f2w  = (const float*)d_in[14];
    const float* f2b  = (const float*)d_in[15];
    const float* opw  = (const float*)d_in[16];
    const float* opb  = (const float*)d_in[17];
    const float* rw   = (const float*)d_in[18];
    const float* pw1  = (const float*)d_in[19];
    const float* pb1  = (const float*)d_in[20];
    const float* pw2  = (const float*)d_in[21];
    const float* pb2  = (const float*)d_in[22];
    const float* pemb = (const float*)d_in[23];
    const int*   mt   = (const int*)d_in[24];
    float* out = (float*)d_out;

    static int smem_set = 0;
    if (!smem_set){
        cudaFuncSetAttribute(mm16<0,0>, cudaFuncAttributeMaxDynamicSharedMemorySize, SMEM_B128);
        cudaFuncSetAttribute(mm16<0,1>, cudaFuncAttributeMaxDynamicSharedMemorySize, SMEM_B128);
        cudaFuncSetAttribute(mm16<0,2>, cudaFuncAttributeMaxDynamicSharedMemorySize, SMEM_B128);
        cudaFuncSetAttribute(mm16<1,2>, cudaFuncAttributeMaxDynamicSharedMemorySize, SMEM_B128);
        cudaFuncSetAttribute(mm16_ln,   cudaFuncAttributeMaxDynamicSharedMemorySize, SMEM_LN_BYTES);
        smem_set = 1;
    }

    void* p;
    cudaGetSymbolAddress(&p, d_bc);     float* bc   = (float*)p;
    cudaGetSymbolAddress(&p, d_cnt);    int*   cnt  = (int*)p;
    cudaGetSymbolAddress(&p, d_xbuf);   float* xb   = (float*)p;
    cudaGetSymbolAddress(&p, d_genb);   float* genb = (float*)p;
    cudaGetSymbolAddress(&p, d_prior_h);float* ph   = (float*)p;
    cudaGetSymbolAddress(&p, d_prior);  float* pr   = (float*)p;
    cudaGetSymbolAddress(&p, d_srcC16); __nv_bfloat16* srcC16 = (__nv_bfloat16*)p;
    cudaGetSymbolAddress(&p, d_tgtC16); __nv_bfloat16* tgtC16 = (__nv_bfloat16*)p;
    cudaGetSymbolAddress(&p, d_x16);    __nv_bfloat16* x16    = (__nv_bfloat16*)p;
    cudaGetSymbolAddress(&p, d_hb16);   __nv_bfloat16* hb16   = (__nv_bfloat16*)p;
    cudaGetSymbolAddress(&p, d_aow16);  __nv_bfloat16* aow16  = (__nv_bfloat16*)p;
    cudaGetSymbolAddress(&p, d_wvT16);  __nv_bfloat16* wvT16  = (__nv_bfloat16*)p;
    cudaGetSymbolAddress(&p, d_Wc16);   __nv_bfloat16* Wc16   = (__nv_bfloat16*)p;
    cudaGetSymbolAddress(&p, d_ipw16);  __nv_bfloat16* ipw16  = (__nv_bfloat16*)p;
    cudaGetSymbolAddress(&p, d_opw16);  __nv_bfloat16* opw16  = (__nv_bfloat16*)p;
    cudaGetSymbolAddress(&p, d_f1w16);  __nv_bfloat16* f1w16  = (__nv_bfloat16*)p;
    cudaGetSymbolAddress(&p, d_f2w16);  __nv_bfloat16* f2w16  = (__nv_bfloat16*)p;

    const size_t HH  = (size_t)HD*HD;
    const size_t SH  = (size_t)SEG*HD;
    const size_t SH4 = (size_t)SEG*HD4;

    // 1) compaction + gather
    build_index_kernel<<<1,256>>>(mt);
    gather_kernel<<<dim3(BSZ,2),128>>>(img, text);

    // 2) one merged weight-conversion launch
    {
        int nf1 = (int)((size_t)6*HD4*HD);
        int gx  = (nf1/4 + 255)/256;
        cvt_all_kernel<<<dim3(gx,5),256>>>(
            aow, aow16, (int)(6*HH),
            ipw, ipw16, (int)(2*HH),
            opw, opw16, (int)(2*HH),
            f1w, f1w16, nf1,
            f2w, f2w16, nf1);
    }
    transpose_wv_kernel<<<dim3(16,16,6), dim3(32,8)>>>(qkvw);

    const dim3 gN512 (HD /BN, BSZ/128, 2);
    const dim3 gN2048(HD4/BN, BSZ/128, 2);
    const dim3 gLN   (1, BSZ/BMF, 2);

    // Wc16[z] = aow16[z] @ wvT16[z]^T   (launch #5)
    mm16<0,2><<<dim3(HD/BN, HD/128, 6), 256, SMEM_B128>>>(
        aow16, HH, wvT16, HH, nullptr, 0, nullptr, Wc16, HH, HD, HD, HD, nullptr);
    // x = srcC @ ipw^T + ipb   (fp32 + bf16 shadow)   (launch #6 — ncu target)
    mm16<0,1><<<gN512,256,SMEM_B128>>>(srcC16, SH, ipw16, HH, ipb, HD,
                                       xb, x16, SH, HD, HD, 0, cnt);

    // small prep that only needs to precede the attention / final kernels
    bc_kernel<<<dim3(6,64),256>>>(aow, aob, qkvb);
    prior_mm_kernel<<<128,256>>>(pemb, pw1, pb1, ph, HD,   2*HD, 1);
    prior_mm_kernel<<<128,256>>>(ph,   pw2, pb2, pr, 2*HD, 2*HD, 0);

    for (int l=0;l<NL;l++){
        // x = LN1( x + tgtC @ Wc[l]^T + bc[l] )
        mm16_ln<<<gLN,256,SMEM_LN_BYTES>>>(tgtC16, SH, Wc16 + (size_t)l*HH, (size_t)NL*HH,
                                  bc + (size_t)l*HD, (size_t)NL*HD,
                                  xb, SH,
                                  ln1g + (size_t)l*HD, ln1b + (size_t)l*HD, (size_t)NL*HD,
                                  xb, x16, SH, HD, cnt);
        // h = gelu(x @ f1w^T + f1b)   (bf16 only)
        mm16<1,2><<<gN2048,256,SMEM_B128>>>(x16, SH, f1w16 + (size_t)l*HD4*HD, (size_t)NL*HD4*HD,
                                   f1b + (size_t)l*HD4, (size_t)NL*HD4,
                                   nullptr, hb16, SH4, HD4, HD, 0, cnt);
        // x = LN2( x + h @ f2w^T + f2b )
        mm16_ln<<<gLN,256,SMEM_LN_BYTES>>>(hb16, SH4, f2w16 + (size_t)l*HD*HD4, (size_t)NL*HD*HD4,
                                  f2b + (size_t)l*HD, (size_t)NL*HD,
                                  xb, SH,
                                  ln2g + (size_t)l*HD, ln2b + (size_t)l*HD, (size_t)NL*HD,
                                  xb, x16, SH, HD4, cnt);
    }
    // gen core = x @ opw^T + opb   (fp32 only)
    mm16<0,0><<<gN512,256,SMEM_B128>>>(x16, SH, opw16, HH, opb, HD,
                                       genb, nullptr, SH, HD, HD, 0, cnt);

    // 3) final selection/blend
    final_kernel<<<BSZ,128>>>(img, text, mt, rw, out);
}

// round 13
// speedup vs baseline: 1.0104x; 1.0104x over previous
#include <cuda_runtime.h>
#include <cuda_bf16.h>
#include <math.h>
#include <cstdint>
#include <stdint.h>

#define BSZ 16384
#define HD 512
#define NL 3
#define HD4 2048
#define SEG BSZ

// bf16 GEMM tiles
#define BN 128
#define BK 64                         // elements
#define PADE 72                       // smem row stride in bf16 elements (144B)
#define SMEM_B128 (3*(128+BN)*PADE*2) // 3-stage, BM=128

// fused GEMM+LN tile: 64 x 512, 2-stage
#define BMF 64
#define STF_EL ((BMF+HD)*PADE)
#define SMEM_LN_BYTES (2*STF_EL*2)

// ---------------- scratch ----------------
__device__ float d_bc[6*HD];
__device__ int   d_cnt[2];
__device__ int   d_idx[2][BSZ];
__device__ int   d_pos[2][BSZ];
__device__ float d_xbuf[(size_t)2*SEG*HD];
__device__ float d_genb[(size_t)2*SEG*HD];
__device__ float d_prior_h[2*HD];
__device__ float d_prior  [2*HD];

__device__ __align__(16) __nv_bfloat16 d_srcC16[(size_t)2*SEG*HD];
__device__ __align__(16) __nv_bfloat16 d_tgtC16[(size_t)2*SEG*HD];
__device__ __align__(16) __nv_bfloat16 d_x16  [(size_t)2*SEG*HD];
__device__ __align__(16) __nv_bfloat16 d_hb16 [(size_t)2*SEG*HD4];
__device__ __align__(16) __nv_bfloat16 d_aow16[(size_t)6*HD*HD];
__device__ __align__(16) __nv_bfloat16 d_wvT16[(size_t)6*HD*HD];
__device__ __align__(16) __nv_bfloat16 d_Wc16 [(size_t)6*HD*HD];
__device__ __align__(16) __nv_bfloat16 d_ipw16[(size_t)2*HD*HD];
__device__ __align__(16) __nv_bfloat16 d_opw16[(size_t)2*HD*HD];
__device__ __align__(16) __nv_bfloat16 d_f1w16[(size_t)6*HD4*HD];
__device__ __align__(16) __nv_bfloat16 d_f2w16[(size_t)6*HD*HD4];

// ---------------- helpers ----------------
__device__ __forceinline__ float gelu_exact(float x){
    return 0.5f*x*(1.0f+erff(x*0.70710678118654752440f));
}
__device__ __forceinline__ unsigned int packbf(float a, float b){
    __nv_bfloat162 p; p.x = __float2bfloat16_rn(a); p.y = __float2bfloat16_rn(b);
    return *reinterpret_cast<unsigned int*>(&p);
}
__device__ __forceinline__ void cpasync16(unsigned int s, const void* g){
    asm volatile("cp.async.cg.shared.global [%0], [%1], 16;\n" :: "r"(s), "l"(g));
}
__device__ __forceinline__ void cpasync_commit(){
    asm volatile("cp.async.commit_group;\n");
}
__device__ __forceinline__ void cpasync_wait1(){
    asm volatile("cp.async.wait_group 1;\n" ::: "memory");
}
__device__ __forceinline__ void cpasync_wait0(){
    asm volatile("cp.async.wait_group 0;\n" ::: "memory");
}
__device__ __forceinline__ void ldsm_x4(unsigned int a, unsigned int &r0, unsigned int &r1,
                                        unsigned int &r2, unsigned int &r3){
    asm volatile("ldmatrix.sync.aligned.m8n8.x4.shared.b16 {%0,%1,%2,%3}, [%4];"
                 : "=r"(r0),"=r"(r1),"=r"(r2),"=r"(r3) : "r"(a));
}
__device__ __forceinline__ void mma_bf16(float* d, const unsigned int* a, const unsigned int* b){
    asm volatile(
        "mma.sync.aligned.m16n8k16.row.col.f32.bf16.bf16.f32 "
        "{%0,%1,%2,%3}, {%4,%5,%6,%7}, {%8,%9}, {%0,%1,%2,%3};"
        : "+f"(d[0]),"+f"(d[1]),"+f"(d[2]),"+f"(d[3])
        : "r"(a[0]),"r"(a[1]),"r"(a[2]),"r"(a[3]),"r"(b[0]),"r"(b[1]));
}

// ---------------- bf16 GEMM: C[z][M,N] = A[z]@W[z]^T + bias ----------------
// EPI: 0 none, 1 gelu.  OUTM: 0 fp32 only, 1 fp32+bf16 shadow, 2 bf16 only.
// BM=128 x BN=128, 3-stage cp.async ring, one __syncthreads per K-iteration.
template<int EPI, int OUTM>
__global__ void __launch_bounds__(256, 2) mm16(
    const __nv_bfloat16* __restrict__ A, size_t As_,
    const __nv_bfloat16* __restrict__ W, size_t Ws_,
    const float* __restrict__ bias, size_t bs_,
    float* __restrict__ C, __nv_bfloat16* __restrict__ C16, size_t Cs_,
    int N, int K, int Mstatic, const int* __restrict__ cnt)
{
    constexpr int TBM = 128;
    constexpr int STG = (TBM+BN)*PADE;

    const int z  = blockIdx.z;
    const int Mv = cnt ? cnt[z] : Mstatic;
    const int m0 = blockIdx.y * TBM;
    if (m0 >= Mv) return;
    const int n0 = blockIdx.x * BN;
    A += (size_t)z * As_;
    W += (size_t)z * Ws_;
    if (OUTM != 2) C   += (size_t)z * Cs_;
    if (OUTM != 0) C16 += (size_t)z * Cs_;
    const float* bptr = bias ? (bias + (size_t)z * bs_) : nullptr;

    extern __shared__ __nv_bfloat16 smem16[];
    const unsigned int smem_u32 = (unsigned int)__cvta_generic_to_shared(smem16);

    const int tid  = threadIdx.x;
    const int wid  = tid >> 5;
    const int lane = tid & 31;
    const int wm   = wid & 1;
    const int wn   = wid >> 1;

    const int arow = (lane & 7) + ((lane >> 3) & 1) * 8;
    const int acol = ((lane >> 4) & 1) * 8;
    const int brow = (lane & 7) + ((lane >> 4) & 1) * 8;
    const int bcol = ((lane >> 3) & 1) * 8;

    unsigned int a_off[4], b_off[2];
    #pragma unroll
    for (int i=0;i<4;i++) a_off[i] = (unsigned int)(((wm*64 + i*16 + arow)*PADE + acol)*2);
    #pragma unroll
    for (int p=0;p<2;p++) b_off[p] = (unsigned int)((TBM*PADE + (wn*32 + p*16 + brow)*PADE + bcol)*2);

    float acc[4][4][4];
    #pragma unroll
    for (int i=0;i<4;i++)
        #pragma unroll
        for (int j=0;j<4;j++)
            #pragma unroll
            for (int r=0;r<4;r++) acc[i][j][r]=0.f;

    auto load_stage = [&](int s, int k0){
        const unsigned int base = smem_u32 + (unsigned int)(s*STG*2);
        #pragma unroll
        for (int it=0; it<4; it++){
            int c  = tid + it*256;          // 0..1023
            int r  = c >> 3;                // 0..127
            int kq = (c & 7) * 8;
            unsigned int off = (unsigned int)((r*PADE + kq)*2);
            cpasync16(base + off,                                  &A[(size_t)(m0+r)*K + k0 + kq]);
            cpasync16(base + (unsigned int)(TBM*PADE*2) + off,     &W[(size_t)(n0+r)*K + k0 + kq]);
        }
        cpasync_commit();
    };

    const int NIT = K / BK;
    load_stage(0, 0);
    load_stage(1, BK);

    for (int i=0; i<NIT; i++){
        if (i < NIT-1) cpasync_wait1(); else cpasync_wait0();
        __syncthreads();
        if (i + 2 < NIT) load_stage((i+2)%3, (i+2)*BK);

        const unsigned int sb = smem_u32 + (unsigned int)((i%3)*STG*2);
        #pragma unroll
        for (int kk=0; kk<BK; kk+=16){
            unsigned int a[4][4], b[4][2];
            #pragma unroll
            for (int ii=0;ii<4;ii++)
                ldsm_x4(sb + a_off[ii] + (unsigned int)(kk*2), a[ii][0],a[ii][1],a[ii][2],a[ii][3]);
            #pragma unroll
            for (int p=0;p<2;p++)
                ldsm_x4(sb + b_off[p] + (unsigned int)(kk*2),
                        b[2*p][0], b[2*p][1], b[2*p+1][0], b[2*p+1][1]);
            #pragma unroll
            for (int ii=0;ii<4;ii++)
                #pragma unroll
                for (int j=0;j<4;j++)
                    mma_bf16(acc[ii][j], a[ii], b[j]);
        }
    }

    const int g   = lane >> 2;
    const int tig = lane & 3;
    #pragma unroll
    for (int i=0;i<4;i++){
        int row0 = m0 + wm*64 + i*16 + g;
        int row1 = row0 + 8;
        #pragma unroll
        for (int j=0;j<4;j++){
            int col = n0 + wn*32 + j*8 + 2*tig;
            float b0 = bptr ? bptr[col]   : 0.f;
            float b1 = bptr ? bptr[col+1] : 0.f;
            float v0 = acc[i][j][0] + b0, v1 = acc[i][j][1] + b1;
            float v2 = acc[i][j][2] + b0, v3 = acc[i][j][3] + b1;
            if (EPI==1){ v0=gelu_exact(v0); v1=gelu_exact(v1); v2=gelu_exact(v2); v3=gelu_exact(v3); }
            if (row0 < Mv){
                if (OUTM != 2) *(float2*)&C[(size_t)row0*N + col] = make_float2(v0,v1);
                if (OUTM != 0) *(unsigned int*)&C16[(size_t)row0*N + col] = packbf(v0,v1);
            }
            if (row1 < Mv){
                if (OUTM != 2) *(float2*)&C[(size_t)row1*N + col] = make_float2(v2,v3);
                if (OUTM != 0) *(unsigned int*)&C16[(size_t)row1*N + col] = packbf(v2,v3);
            }
        }
    }
}

// ---------------- fused bf16 GEMM + residual + LayerNorm (N = 512) ----------------
__global__ void __launch_bounds__(256, 1) mm16_ln(
    const __nv_bfloat16* __restrict__ A, size_t As_,
    const __nv_bfloat16* __restrict__ W, size_t Ws_,
    const float* __restrict__ bias, size_t bs_,
    const float* __restrict__ Xres, size_t Xs_,
    const float* __restrict__ lng, const float* __restrict__ lnb, size_t lns_,
    float* __restrict__ Out, __nv_bfloat16* __restrict__ Out16, size_t Os_,
    int K, const int* __restrict__ cnt)
{
    const int z  = blockIdx.z;
    const int Mv = cnt[z];
    const int m0 = blockIdx.y * BMF;
    if (m0 >= Mv) return;
    A     += (size_t)z * As_;
    W     += (size_t)z * Ws_;
    Xres  += (size_t)z * Xs_;
    Out   += (size_t)z * Os_;
    Out16 += (size_t)z * Os_;
    const float* bptr = bias + (size_t)z * bs_;
    const float* gptr = lng  + (size_t)z * lns_;
    const float* hptr = lnb  + (size_t)z * lns_;

    extern __shared__ __nv_bfloat16 smem16[];
    const unsigned int smem_u32 = (unsigned int)__cvta_generic_to_shared(smem16);
    float* smf = reinterpret_cast<float*>(smem16);

    const int tid  = threadIdx.x;
    const int wid  = tid >> 5;
    const int lane = tid & 31;
    const int wm   = wid & 1;     // 2 m-halves of 32
    const int wn   = wid >> 1;    // 4 n-quarters of 128

    const int arow = (lane & 7) + ((lane >> 3) & 1) * 8;
    const int acol = ((lane >> 4) & 1) * 8;
    const int brow = (lane & 7) + ((lane >> 4) & 1) * 8;
    const int bcol = ((lane >> 3) & 1) * 8;

    unsigned int a_off[2], b_off[8];
    #pragma unroll
    for (int i=0;i<2;i++) a_off[i] = (unsigned int)(((wm*32 + i*16 + arow)*PADE + acol)*2);
    #pragma unroll
    for (int p=0;p<8;p++) b_off[p] = (unsigned int)((BMF*PADE + (wn*128 + p*16 + brow)*PADE + bcol)*2);

    float acc[2][16][4];
    #pragma unroll
    for (int i=0;i<2;i++)
        #pragma unroll
        for (int j=0;j<16;j++)
            #pragma unroll
            for (int r=0;r<4;r++) acc[i][j][r]=0.f;

    auto load_stage = [&](int s, int k0){
        const unsigned int base = smem_u32 + (unsigned int)(s*STF_EL*2);
        #pragma unroll
        for (int it=0; it<2; it++){
            int c  = tid + it*256;
            int r  = c >> 3;
            int kq = (c & 7) * 8;
            cpasync16(base + (unsigned int)((r*PADE + kq)*2), &A[(size_t)(m0+r)*K + k0 + kq]);
        }
        #pragma unroll
        for (int it=0; it<16; it++){
            int c  = tid + it*256;
            int r  = c >> 3;
            int kq = (c & 7) * 8;
            cpasync16(base + (unsigned int)((BMF*PADE + r*PADE + kq)*2), &W[(size_t)r*K + k0 + kq]);
        }
        cpasync_commit();
    };

    const int NIT = K / BK;
    load_stage(0, 0);

    for (int i=0; i<NIT; i++){
        cpasync_wait0();
        __syncthreads();
        if (i + 1 < NIT) load_stage((i+1)&1, (i+1)*BK);

        const unsigned int sb = smem_u32 + (unsigned int)((i&1)*STF_EL*2);
        #pragma unroll
        for (int kk=0; kk<BK; kk+=16){
            unsigned int a[2][4], b[16][2];
            #pragma unroll
            for (int ii=0;ii<2;ii++)
                ldsm_x4(sb + a_off[ii] + (unsigned int)(kk*2), a[ii][0],a[ii][1],a[ii][2],a[ii][3]);
            #pragma unroll
            for (int p=0;p<8;p++)
                ldsm_x4(sb + b_off[p] + (unsigned int)(kk*2),
                        b[2*p][0], b[2*p][1], b[2*p+1][0], b[2*p+1][1]);
            #pragma unroll
            for (int ii=0;ii<2;ii++)
                #pragma unroll
                for (int j=0;j<16;j++)
                    mma_bf16(acc[ii][j], a[ii], b[j]);
        }
    }
    __syncthreads();

    const int g   = lane >> 2;
    const int tig = lane & 3;
    #pragma unroll
    for (int i=0;i<2;i++){
        int row0 = m0 + wm*32 + i*16 + g;
        int row1 = row0 + 8;
        #pragma unroll
        for (int j=0;j<16;j++){
            int col = wn*128 + j*8 + 2*tig;
            float b0 = bptr[col], b1 = bptr[col+1];
            if (row0 < Mv){
                float2 x = *(const float2*)&Xres[(size_t)row0*HD + col];
                acc[i][j][0] += b0 + x.x;
                acc[i][j][1] += b1 + x.y;
            }
            if (row1 < Mv){
                float2 x = *(const float2*)&Xres[(size_t)row1*HD + col];
                acc[i][j][2] += b0 + x.x;
                acc[i][j][3] += b1 + x.y;
            }
        }
    }

    float S[2][2], Q[2][2];
    #pragma unroll
    for (int i=0;i<2;i++)
        #pragma unroll
        for (int h=0;h<2;h++){
            float s=0.f, q=0.f;
            #pragma unroll
            for (int j=0;j<16;j++){
                float v0=acc[i][j][2*h], v1=acc[i][j][2*h+1];
                s += v0+v1; q += v0*v0+v1*v1;
            }
            s += __shfl_xor_sync(0xffffffffu, s, 1);
            s += __shfl_xor_sync(0xffffffffu, s, 2);
            q += __shfl_xor_sync(0xffffffffu, q, 1);
            q += __shfl_xor_sync(0xffffffffu, q, 2);
            S[i][h]=s; Q[i][h]=q;
        }
    float* redS = smf;
    float* redQ = smf + 256;
    if (tig==0){
        #pragma unroll
        for (int i=0;i<2;i++)
            #pragma unroll
            for (int h=0;h<2;h++){
                int lr = wm*32 + i*16 + g + h*8;
                redS[lr*4+wn] = S[i][h];
                redQ[lr*4+wn] = Q[i][h];
            }
    }
    __syncthreads();

    #pragma unroll
    for (int i=0;i<2;i++){
        #pragma unroll
        for (int h=0;h<2;h++){
            int lr  = wm*32 + i*16 + g + h*8;
            int row = m0 + lr;
            if (row >= Mv) continue;
            float s = redS[lr*4+0]+redS[lr*4+1]+redS[lr*4+2]+redS[lr*4+3];
            float q = redQ[lr*4+0]+redQ[lr*4+1]+redQ[lr*4+2]+redQ[lr*4+3];
            float mean = s*(1.f/512.f);
            float var  = q*(1.f/512.f) - mean*mean;
            float rs   = rsqrtf(var + 1e-5f);
            #pragma unroll
            for (int j=0;j<16;j++){
                int col = wn*128 + j*8 + 2*tig;
                float g0=gptr[col], g1=gptr[col+1], h0=hptr[col], h1=hptr[col+1];
                float v0=(acc[i][j][2*h  ]-mean)*rs*g0+h0;
                float v1=(acc[i][j][2*h+1]-mean)*rs*g1+h1;
                *(float2*)&Out[(size_t)row*HD + col] = make_float2(v0,v1);
                *(unsigned int*)&Out16[(size_t)row*HD + col] = packbf(v0,v1);
            }
        }
    }
}

// ---------------- flat right-sized weight conversion (5 segments, 1 launch) ----------------
// Chunk counts (float4 units): c0=393216, c1=131072, c2=131072, c3=1572864, c4=1572864
#define CVT_B0 393216
#define CVT_B1 (CVT_B0+131072)
#define CVT_B2 (CVT_B1+131072)
#define CVT_B3 (CVT_B2+1572864)
#define CVT_B4 (CVT_B3+1572864)   // total 3,801,088 chunks -> 14848 blocks @256
__global__ void cvt_flat_kernel(
    const float* s0, __nv_bfloat16* d0,
    const float* s1, __nv_bfloat16* d1,
    const float* s2, __nv_bfloat16* d2,
    const float* s3, __nv_bfloat16* d3,
    const float* s4, __nv_bfloat16* d4)
{
    int cid = blockIdx.x*blockDim.x + threadIdx.x;
    if (cid >= CVT_B4) return;
    const float* s; __nv_bfloat16* d; int base;
    if      (cid < CVT_B0){ s=s0; d=d0; base=0; }
    else if (cid < CVT_B1){ s=s1; d=d1; base=CVT_B0; }
    else if (cid < CVT_B2){ s=s2; d=d2; base=CVT_B1; }
    else if (cid < CVT_B3){ s=s3; d=d3; base=CVT_B2; }
    else                  { s=s4; d=d4; base=CVT_B3; }
    int i = (cid - base)*4;
    float4 v = *(const float4*)&s[i];
    *(uint2*)&d[i] = make_uint2(packbf(v.x,v.y), packbf(v.z,v.w));
}

// ---------------- misc kernels ----------------
__global__ void build_index_kernel(const int* __restrict__ mt)
{
    if (threadIdx.x==0){ d_cnt[0]=0; d_cnt[1]=0; }
    __syncthreads();
    for (int b=threadIdx.x; b<BSZ; b+=blockDim.x){
        int m = mt[b];
        if (m==1){ int p=atomicAdd(&d_cnt[0],1); d_idx[0][p]=b; d_pos[0][b]=p; }
        else if (m==2){ int p=atomicAdd(&d_cnt[1],1); d_idx[1][p]=b; d_pos[1][b]=p; }
    }
}

__global__ void __launch_bounds__(128) gather_kernel(
    const float* __restrict__ img, const float* __restrict__ text)
{
    int gi = blockIdx.y;
    int c  = blockIdx.x;
    if (c >= d_cnt[gi]) return;
    int r = d_idx[gi][c];
    const float* src = gi ? text : img;
    const float* tgt = gi ? img  : text;
    int t = threadIdx.x;
    size_t drow = (size_t)gi*SEG + c;
    float4 sv = ((const float4*)src)[(size_t)r*128+t];
    float4 tv = ((const float4*)tgt)[(size_t)r*128+t];
    *(uint2*)&d_srcC16[drow*HD + t*4] = make_uint2(packbf(sv.x,sv.y), packbf(sv.z,sv.w));
    *(uint2*)&d_tgtC16[drow*HD + t*4] = make_uint2(packbf(tv.x,tv.y), packbf(tv.z,tv.w));
}

__global__ void transpose_wv_kernel(const float* __restrict__ qkv_w)
{
    __shared__ float tile[32][33];
    int bz = blockIdx.z;
    const float* src = qkv_w + (size_t)bz*3*HD*HD + (size_t)2*HD*HD;
    int j0 = blockIdx.y*32, k0 = blockIdx.x*32;
    int tx = threadIdx.x, ty = threadIdx.y;
    #pragma unroll
    for (int r=0;r<32;r+=8)
        tile[ty+r][tx] = src[(size_t)(j0+ty+r)*HD + k0+tx];
    __syncthreads();
    __nv_bfloat16* dst = d_wvT16 + (size_t)bz*HD*HD;
    #pragma unroll
    for (int r=0;r<32;r+=8)
        dst[(size_t)(k0+ty+r)*HD + j0+tx] = __float2bfloat16_rn(tile[tx][ty+r]);
}

__global__ void __launch_bounds__(256) bc_kernel(const float* __restrict__ ao_w,
                          const float* __restrict__ ao_b,
                          const float* __restrict__ qkv_b)
{
    int z = blockIdx.x;
    int n = blockIdx.y*8 + (threadIdx.x>>5);
    int lane = threadIdx.x&31;
    const float* ao = ao_w + (size_t)z*HD*HD + (size_t)n*HD;
    const float* bv = qkv_b + (size_t)z*3*HD + 2*HD;
    float s=0.f;
    #pragma unroll
    for (int j=lane*4;j<HD;j+=128){
        float4 a = *(const float4*)&ao[j];
        float4 b = *(const float4*)&bv[j];
        s += a.x*b.x + a.y*b.y + a.z*b.z + a.w*b.w;
    }
    #pragma unroll
    for (int off=16;off;off>>=1) s += __shfl_down_sync(0xffffffffu,s,off);
    if (lane==0) d_bc[(size_t)z*HD+n] = s + ao_b[(size_t)z*HD+n];
}

__global__ void prior_mm_kernel(const float* __restrict__ x, const float* __restrict__ W,
                                const float* __restrict__ b, float* __restrict__ out,
                                int K, int N, int dogelu)
{
    int gw = (blockIdx.x*blockDim.x + threadIdx.x)>>5;
    int lane = threadIdx.x & 31;
    if (gw >= N) return;
    float s=0.f;
    for (int k=lane;k<K;k+=32) s += x[k]*W[(size_t)gw*K+k];
    #pragma unroll
    for (int off=16;off;off>>=1) s += __shfl_down_sync(0xffffffffu,s,off);
    if (lane==0){ s += b[gw]; out[gw] = dogelu ? gelu_exact(s) : s; }
}

__global__ void __launch_bounds__(128) final_kernel(
    const float* __restrict__ img, const float* __restrict__ text,
    const int* __restrict__ mtA, const float* __restrict__ rw,
    float* __restrict__ out)
{
    int b = blockIdx.x, t = threadIdx.x;
    int mt = mtA[b];
    float4 iv = ((const float4*)img )[(size_t)b*128+t];
    float4 tv = ((const float4*)text)[(size_t)b*128+t];
    float4 oi = iv, ot = tv;
    if (mt==3){
        oi = ((const float4*)d_prior)[t];
        ot = ((const float4*)d_prior)[128+t];
    } else if (mt==2){
        float r = rw[1], q = 1.f - r;
        float4 gv = ((const float4*)d_genb)[((size_t)SEG + d_pos[1][b])*128+t];
        oi.x=r*iv.x+q*gv.x; oi.y=r*iv.y+q*gv.y; oi.z=r*iv.z+q*gv.z; oi.w=r*iv.w+q*gv.w;
    } else if (mt==1){
        float r = rw[0], q = 1.f - r;
        float4 gv = ((const float4*)d_genb)[(size_t)d_pos[0][b]*128+t];
        ot.x=r*tv.x+q*gv.x; ot.y=r*tv.y+q*gv.y; ot.z=r*tv.z+q*gv.z; ot.w=r*tv.w+q*gv.w;
    }
    ((float4*)out)[(size_t)b*128+t] = oi;
    ((float4*)out)[(size_t)BSZ*128 + (size_t)b*128+t] = ot;
}

// ---------------- host orchestration (R10 order) ----------------
extern "C" void kernel_launch(void* const* d_in, const int* in_sizes, int n_in,
                              void* d_out, int out_size)
{
    const float* img  = (const float*)d_in[0];
    const float* text = (const float*)d_in[1];
    const float* ipw  = (const float*)d_in[2];
    const float* ipb  = (const float*)d_in[3];
    const float* qkvw = (const float*)d_in[4];
    const float* qkvb = (const float*)d_in[5];
    const float* aow  = (const float*)d_in[6];
    const float* aob  = (const float*)d_in[7];
    const float* ln1g = (const float*)d_in[8];
    const float* ln1b = (const float*)d_in[9];
    const float* ln2g = (const float*)d_in[10];
    const float* ln2b = (const float*)d_in[11];
    const float* f1w  = (const float*)d_in[12];
    const float* f1b  = (const float*)d_in[13];
    const float* f2w  = (const float*)d_in[14];
    const float* f2b  = (const float*)d_in[15];
    const float* opw  = (const float*)d_in[16];
    const float* opb  = (const float*)d_in[17];
    const float* rw   = (const float*)d_in[18];
    const float* pw1  = (const float*)d_in[19];
    const float* pb1  = (const float*)d_in[20];
    const float* pw2  = (const float*)d_in[21];
    const float* pb2  = (const float*)d_in[22];
    const float* pemb = (const float*)d_in[23];
    const int*   mt   = (const int*)d_in[24];
    float* out = (float*)d_out;

    static int smem_set = 0;
    if (!smem_set){
        cudaFuncSetAttribute(mm16<0,0>, cudaFuncAttributeMaxDynamicSharedMemorySize, SMEM_B128);
        cudaFuncSetAttribute(mm16<0,1>, cudaFuncAttributeMaxDynamicSharedMemorySize, SMEM_B128);
        cudaFuncSetAttribute(mm16<0,2>, cudaFuncAttributeMaxDynamicSharedMemorySize, SMEM_B128);
        cudaFuncSetAttribute(mm16<1,2>, cudaFuncAttributeMaxDynamicSharedMemorySize, SMEM_B128);
        cudaFuncSetAttribute(mm16_ln,   cudaFuncAttributeMaxDynamicSharedMemorySize, SMEM_LN_BYTES);
        smem_set = 1;
    }

    void* p;
    cudaGetSymbolAddress(&p, d_bc);     float* bc   = (float*)p;
    cudaGetSymbolAddress(&p, d_cnt);    int*   cnt  = (int*)p;
    cudaGetSymbolAddress(&p, d_xbuf);   float* xb   = (float*)p;
    cudaGetSymbolAddress(&p, d_genb);   float* genb = (float*)p;
    cudaGetSymbolAddress(&p, d_prior_h);float* ph   = (float*)p;
    cudaGetSymbolAddress(&p, d_prior);  float* pr   = (float*)p;
    cudaGetSymbolAddress(&p, d_srcC16); __nv_bfloat16* srcC16 = (__nv_bfloat16*)p;
    cudaGetSymbolAddress(&p, d_tgtC16); __nv_bfloat16* tgtC16 = (__nv_bfloat16*)p;
    cudaGetSymbolAddress(&p, d_x16);    __nv_bfloat16* x16    = (__nv_bfloat16*)p;
    cudaGetSymbolAddress(&p, d_hb16);   __nv_bfloat16* hb16   = (__nv_bfloat16*)p;
    cudaGetSymbolAddress(&p, d_aow16);  __nv_bfloat16* aow16  = (__nv_bfloat16*)p;
    cudaGetSymbolAddress(&p, d_wvT16);  __nv_bfloat16* wvT16  = (__nv_bfloat16*)p;
    cudaGetSymbolAddress(&p, d_Wc16);   __nv_bfloat16* Wc16   = (__nv_bfloat16*)p;
    cudaGetSymbolAddress(&p, d_ipw16);  __nv_bfloat16* ipw16  = (__nv_bfloat16*)p;
    cudaGetSymbolAddress(&p, d_opw16);  __nv_bfloat16* opw16  = (__nv_bfloat16*)p;
    cudaGetSymbolAddress(&p, d_f1w16);  __nv_bfloat16* f1w16  = (__nv_bfloat16*)p;
    cudaGetSymbolAddress(&p, d_f2w16);  __nv_bfloat16* f2w16  = (__nv_bfloat16*)p;

    const size_t HH  = (size_t)HD*HD;
    const size_t SH  = (size_t)SEG*HD;
    const size_t SH4 = (size_t)SEG*HD4;

    // 1) compaction + weight conversion (one flat launch) + prep + prior  (R10 order)
    build_index_kernel<<<1,256>>>(mt);
    cvt_flat_kernel<<<(CVT_B4 + 255)/256, 256>>>(
        aow, aow16, ipw, ipw16, opw, opw16, f1w, f1w16, f2w, f2w16);
    transpose_wv_kernel<<<dim3(16,16,6), dim3(32,8)>>>(qkvw);
    mm16<0,2><<<dim3(HD/BN, HD/128, 6), 256, SMEM_B128>>>(
        aow16, HH, wvT16, HH, nullptr, 0, nullptr, Wc16, HH, HD, HD, HD, nullptr);
    bc_kernel<<<dim3(6,64),256>>>(aow, aob, qkvb);
    prior_mm_kernel<<<128,256>>>(pemb, pw1, pb1, ph, HD,   2*HD, 1);
    prior_mm_kernel<<<128,256>>>(ph,   pw2, pb2, pr, 2*HD, 2*HD, 0);

    // 2) both generators batched over z=2 on compacted rows
    gather_kernel<<<dim3(BSZ,2),128>>>(img, text);

    const dim3 gN512 (HD /BN, BSZ/128, 2);
    const dim3 gN2048(HD4/BN, BSZ/128, 2);
    const dim3 gLN   (1, BSZ/BMF, 2);

    // x = srcC @ ipw^T + ipb   (fp32 + bf16 shadow)
    mm16<0,1><<<gN512,256,SMEM_B128>>>(srcC16, SH, ipw16, HH, ipb, HD,
                                       xb, x16, SH, HD, HD, 0, cnt);
    for (int l=0;l<NL;l++){
        // x = LN1( x + tgtC @ Wc[l]^T + bc[l] )
        mm16_ln<<<gLN,256,SMEM_LN_BYTES>>>(tgtC16, SH, Wc16 + (size_t)l*HH, (size_t)NL*HH,
                                  bc + (size_t)l*HD, (size_t)NL*HD,
                                  xb, SH,
                                  ln1g + (size_t)l*HD, ln1b + (size_t)l*HD, (size_t)NL*HD,
                                  xb, x16, SH, HD, cnt);
        // h = gelu(x @ f1w^T + f1b)   (bf16 only)
        mm16<1,2><<<gN2048,256,SMEM_B128>>>(x16, SH, f1w16 + (size_t)l*HD4*HD, (size_t)NL*HD4*HD,
                                   f1b + (size_t)l*HD4, (size_t)NL*HD4,
                                   nullptr, hb16, SH4, HD4, HD, 0, cnt);
        // x = LN2( x + h @ f2w^T + f2b )
        mm16_ln<<<gLN,256,SMEM_LN_BYTES>>>(hb16, SH4, f2w16 + (size_t)l*HD*HD4, (size_t)NL*HD*HD4,
                                  f2b + (size_t)l*HD, (size_t)NL*HD,
                                  xb, SH,
                                  ln2g + (size_t)l*HD, ln2b + (size_t)l*HD, (size_t)NL*HD,
                                  xb, x16, SH, HD4, cnt);
    }
    // gen core = x @ opw^T + opb   (fp32 only)
    mm16<0,0><<<gN512,256,SMEM_B128>>>(x16, SH, opw16, HH, opb, HD,
                                       genb, nullptr, SH, HD, HD, 0, cnt);

    // 3) final selection/blend
    final_kernel<<<BSZ,128>>>(img, text, mt, rw, out);
}